// round 3
// baseline (speedup 1.0000x reference)
#include <cuda_runtime.h>
#include <cuda_bf16.h>

// Problem constants (B=256 rows, D=512 cols, row-major [B, D])
#define B_ROWS 256
#define D_COLS 512
#define CPB 8                 // columns per block
#define GRID (D_COLS / CPB)   // 64 blocks
#define THREADS 256

// Scratch (no device allocation allowed)
__device__ float g_block_sum[GRID];
__device__ int   g_counter = 0;

__global__ __launch_bounds__(THREADS) void kl_fused_kernel(
    const float* __restrict__ mu, const float* __restrict__ logvar,
    float* __restrict__ out)
{
    const int tid = threadIdx.x;
    const int p   = tid & 1;          // which float4 (cols p*4 .. p*4+3) of the 8
    const int r   = tid >> 1;         // 0..127 row base; rows r and r+128
    const int colbase = blockIdx.x * CPB + p * 4;

    // ---- Phase 1: per-thread partials, 4 columns x 2 rows, vectorized ----
    float s0[4] = {0,0,0,0}, s1[4] = {0,0,0,0}, s2[4] = {0,0,0,0};
    float s3[4] = {0,0,0,0}, s4[4] = {0,0,0,0}, s5[4] = {0,0,0,0};

    #pragma unroll
    for (int k = 0; k < 2; k++) {
        const int i = r + k * 128;
        const float4 m4 = *(const float4*)&mu[i * D_COLS + colbase];
        const float4 l4 = *(const float4*)&logvar[i * D_COLS + colbase];
        const float mm[4] = {m4.x, m4.y, m4.z, m4.w};
        const float ll[4] = {l4.x, l4.y, l4.z, l4.w};
        #pragma unroll
        for (int j = 0; j < 4; j++) {
            const float m  = mm[j];
            const float v  = __expf(ll[j]);
            const float iv = __expf(-ll[j]);
            s0[j] += v;           // sum var
            s1[j] += iv;          // sum 1/var
            s2[j] += m;           // sum mu
            s3[j] += m * m;       // sum mu^2
            s4[j] += m * iv;      // sum mu/var
            s5[j] += m * m * iv;  // sum mu^2/var
        }
    }

    // ---- Warp reduce across rows (parity-preserving: offsets 16,8,4,2) ----
    #pragma unroll
    for (int off = 16; off >= 2; off >>= 1) {
        #pragma unroll
        for (int j = 0; j < 4; j++) {
            s0[j] += __shfl_down_sync(0xFFFFFFFFu, s0[j], off);
            s1[j] += __shfl_down_sync(0xFFFFFFFFu, s1[j], off);
            s2[j] += __shfl_down_sync(0xFFFFFFFFu, s2[j], off);
            s3[j] += __shfl_down_sync(0xFFFFFFFFu, s3[j], off);
            s4[j] += __shfl_down_sync(0xFFFFFFFFu, s4[j], off);
            s5[j] += __shfl_down_sync(0xFFFFFFFFu, s5[j], off);
        }
    }
    // Now lane 0 holds sums for parity 0, lane 1 for parity 1 (16 rows each).

    __shared__ float sh[6][8][2][4];  // [stat][warp][parity][col]
    const int warp = tid >> 5;
    const int lane = tid & 31;
    if (lane < 2) {
        #pragma unroll
        for (int j = 0; j < 4; j++) {
            sh[0][warp][lane][j] = s0[j];
            sh[1][warp][lane][j] = s1[j];
            sh[2][warp][lane][j] = s2[j];
            sh[3][warp][lane][j] = s3[j];
            sh[4][warp][lane][j] = s4[j];
            sh[5][warp][lane][j] = s5[j];
        }
    }
    __syncthreads();

    // ---- Threads 0..7: combine 8 warps, one column each; then 8->1 ----
    float blk = 0.0f;
    if (tid < CPB) {
        const int pp = tid >> 2;   // parity
        const int jj = tid & 3;    // col within float4
        float t0 = 0.f, t1 = 0.f, t2 = 0.f, t3 = 0.f, t4 = 0.f, t5 = 0.f;
        #pragma unroll
        for (int w = 0; w < 8; w++) {
            t0 += sh[0][w][pp][jj]; t1 += sh[1][w][pp][jj]; t2 += sh[2][w][pp][jj];
            t3 += sh[3][w][pp][jj]; t4 += sh[4][w][pp][jj]; t5 += sh[5][w][pp][jj];
        }
        const float Bf = (float)B_ROWS;
        // c_d = S_var*S_inv + S_mu2*S_inv - 2*S_mu*S_muinv + B*S_mu2inv - B^2
        blk = t0 * t1 + t3 * t1 - 2.0f * t2 * t4 + Bf * t5 - Bf * Bf;
    }
    // Reduce 8 column contributions to one block scalar (lanes 0..7 of warp 0)
    if (warp == 0) {
        blk += __shfl_down_sync(0xFFFFFFFFu, blk, 4);
        blk += __shfl_down_sync(0xFFFFFFFFu, blk, 2);
        blk += __shfl_down_sync(0xFFFFFFFFu, blk, 1);
        if (lane == 0) g_block_sum[blockIdx.x] = blk;
    }

    // ---- Last-block final reduce ----
    __shared__ int is_last;
    __threadfence();
    __syncthreads();
    if (tid == 0) {
        int prev = atomicAdd(&g_counter, 1);
        is_last = (prev == GRID - 1);
    }
    __syncthreads();

    if (is_last && tid < 32) {
        float x = __ldcg(&g_block_sum[tid]) + __ldcg(&g_block_sum[tid + 32]);
        #pragma unroll
        for (int off = 16; off > 0; off >>= 1)
            x += __shfl_down_sync(0xFFFFFFFFu, x, off);
        if (tid == 0) {
            out[0] = x * (0.5f / (float)B_ROWS);
            g_counter = 0;  // reset for next graph replay
        }
    }
}

extern "C" void kernel_launch(void* const* d_in, const int* in_sizes, int n_in,
                              void* d_out, int out_size)
{
    const float* mu = (const float*)d_in[0];
    const float* lv = (const float*)d_in[1];
    float* out = (float*)d_out;

    kl_fused_kernel<<<GRID, THREADS>>>(mu, lv, out);
}

// round 4
// speedup vs baseline: 1.2431x; 1.2431x over previous
#include <cuda_runtime.h>
#include <cuda_bf16.h>

// Problem constants (B=256 rows, D=512 cols, row-major [B, D])
#define B_ROWS 256
#define D_COLS 512
#define CPB 8                 // columns per block
#define GRID (D_COLS / CPB)   // 64 blocks
#define THREADS 256
#define RPT (B_ROWS / (THREADS / CPB)) // 8 rows per thread

// Scratch (no device allocation allowed)
__device__ float g_block_sum[GRID];
__device__ int   g_counter = 0;

__global__ __launch_bounds__(THREADS) void kl_fused_kernel(
    const float* __restrict__ mu, const float* __restrict__ logvar,
    float* __restrict__ out)
{
    const int tid = threadIdx.x;
    const int c   = tid & (CPB - 1);       // column within this block's group
    const int rb  = tid >> 3;              // 0..31 row base
    const int d   = blockIdx.x * CPB + c;  // global column

    // ---- Phase 1: issue all loads up-front for max MLP ----
    float mv[RPT], lv_[RPT];
    #pragma unroll
    for (int k = 0; k < RPT; k++) {
        const int i = rb + k * 32;
        mv[k]  = mu[i * D_COLS + d];
        lv_[k] = logvar[i * D_COLS + d];
    }

    float s0 = 0.f, s1 = 0.f, s2 = 0.f, s3 = 0.f, s4 = 0.f, s5 = 0.f;
    #pragma unroll
    for (int k = 0; k < RPT; k++) {
        const float m  = mv[k];
        const float v  = __expf(lv_[k]);
        const float iv = __expf(-lv_[k]);
        s0 += v;          // sum var
        s1 += iv;         // sum 1/var
        s2 += m;          // sum mu
        s3 += m * m;      // sum mu^2
        s4 += m * iv;     // sum mu/var
        s5 += m * m * iv; // sum mu^2/var
    }

    // ---- Warp reduce across row-groups: lanes {c, c+8, c+16, c+24} ----
    #pragma unroll
    for (int off = 16; off >= 8; off >>= 1) {
        s0 += __shfl_down_sync(0xFFFFFFFFu, s0, off);
        s1 += __shfl_down_sync(0xFFFFFFFFu, s1, off);
        s2 += __shfl_down_sync(0xFFFFFFFFu, s2, off);
        s3 += __shfl_down_sync(0xFFFFFFFFu, s3, off);
        s4 += __shfl_down_sync(0xFFFFFFFFu, s4, off);
        s5 += __shfl_down_sync(0xFFFFFFFFu, s5, off);
    }

    __shared__ float sh[6][8][CPB];   // [stat][warp][col]
    const int warp = tid >> 5;
    const int lane = tid & 31;
    if (lane < CPB) {
        sh[0][warp][lane] = s0; sh[1][warp][lane] = s1; sh[2][warp][lane] = s2;
        sh[3][warp][lane] = s3; sh[4][warp][lane] = s4; sh[5][warp][lane] = s5;
    }
    __syncthreads();

    // ---- Threads 0..7: combine 8 warps for one column each ----
    float blk = 0.0f;
    if (tid < CPB) {
        float t0 = 0.f, t1 = 0.f, t2 = 0.f, t3 = 0.f, t4 = 0.f, t5 = 0.f;
        #pragma unroll
        for (int w = 0; w < 8; w++) {
            t0 += sh[0][w][tid]; t1 += sh[1][w][tid]; t2 += sh[2][w][tid];
            t3 += sh[3][w][tid]; t4 += sh[4][w][tid]; t5 += sh[5][w][tid];
        }
        const float Bf = (float)B_ROWS;
        // c_d = S_inv*(S_var + S_mu2) - 2*S_mu*S_muinv + B*S_mu2inv - B^2
        blk = t1 * (t0 + t3) - 2.0f * t2 * t4 + Bf * t5 - Bf * Bf;
    }
    // 8 column contributions -> one block scalar (lanes 0..7 of warp 0)
    if (warp == 0) {
        blk += __shfl_down_sync(0xFFFFFFFFu, blk, 4);
        blk += __shfl_down_sync(0xFFFFFFFFu, blk, 2);
        blk += __shfl_down_sync(0xFFFFFFFFu, blk, 1);
        if (lane == 0) g_block_sum[blockIdx.x] = blk;
    }

    // ---- Last-block final reduce (64 partials, one warp) ----
    __shared__ int is_last;
    __threadfence();
    __syncthreads();
    if (tid == 0) {
        int prev = atomicAdd(&g_counter, 1);
        is_last = (prev == GRID - 1);
    }
    __syncthreads();

    if (is_last && tid < 32) {
        float x = __ldcg(&g_block_sum[tid]) + __ldcg(&g_block_sum[tid + 32]);
        #pragma unroll
        for (int off = 16; off > 0; off >>= 1)
            x += __shfl_down_sync(0xFFFFFFFFu, x, off);
        if (tid == 0) {
            out[0] = x * (0.5f / (float)B_ROWS);
            g_counter = 0;  // reset for next graph replay
        }
    }
}

extern "C" void kernel_launch(void* const* d_in, const int* in_sizes, int n_in,
                              void* d_out, int out_size)
{
    const float* mu = (const float*)d_in[0];
    const float* lv = (const float*)d_in[1];
    float* out = (float*)d_out;

    kl_fused_kernel<<<GRID, THREADS>>>(mu, lv, out);
}